// round 2
// baseline (speedup 1.0000x reference)
#include <cuda_runtime.h>
#include <math.h>

// Problem constants
#define B_  16
#define NN  4096
#define D_  64
#define O_  12
#define S_  32
#define M_  12
#define A_  32
#define TPB 128

// Output layout: H_time [B,O,N,D] ++ attn [B,O,N,M] ++ gate [B,O,M]
#define ATT_OFF  50331648ull   // B*O*N*D
#define GATE_OFF 59768832ull   // + B*O*N*M
#define SCALE 0.17677669529663688f   // 1/sqrt(32)

// Scratch (no allocations allowed -> __device__ globals)
__device__ float g_key[B_*O_*A_*M_];   // [b][o][a][m]  (m contiguous, for f32x2 m-pair logits)
__device__ float g_val[B_*O_*M_*D_];   // [b][o][m][d]  (gate already folded in)
__device__ float g_qs [B_*O_*A_];      // [b][o][a]

// ---- f32x2 helpers (ptxas only emits FFMA2 via PTX fma.rn.f32x2) ----
__device__ __forceinline__ unsigned long long ffma2(unsigned long long a,
                                                    unsigned long long b,
                                                    unsigned long long c) {
    unsigned long long d;
    asm("fma.rn.f32x2 %0, %1, %2, %3;" : "=l"(d) : "l"(a), "l"(b), "l"(c));
    return d;
}
__device__ __forceinline__ unsigned long long pack2(float x, float y) {
    unsigned long long r;
    asm("mov.b64 %0, {%1, %2};" : "=l"(r) : "r"(__float_as_uint(x)), "r"(__float_as_uint(y)));
    return r;
}
__device__ __forceinline__ float2 unpack2(unsigned long long v) {
    unsigned int lo, hi;
    asm("mov.b64 {%0, %1}, %2;" : "=r"(lo), "=r"(hi) : "l"(v));
    return make_float2(__uint_as_float(lo), __uint_as_float(hi));
}

// ============================================================================
// Kernel 1: per-(b,o) tiny precompute (tokens, key, gate, val, qs)
// ============================================================================
__global__ void precompute_kernel(const float* __restrict__ ts_out,
                                  const float* __restrict__ step_emb,
                                  const float* __restrict__ key_emb,
                                  const float* __restrict__ val_emb,
                                  const float* __restrict__ Wk,
                                  const float* __restrict__ Wg,
                                  const float* __restrict__ bg,
                                  const float* __restrict__ Wq,
                                  const float* __restrict__ bq,
                                  float* __restrict__ out) {
    __shared__ float tok_sh[M_ * 2];
    __shared__ float gate_sh[M_];
    const int bx  = blockIdx.x;      // bx = b*O + o
    const int tid = threadIdx.x;

    const float tod = ts_out[bx * 2 + 0];
    const float dow = ts_out[bx * 2 + 1];

    if (tid < M_) {
        const int m   = tid;
        const float ph = (m < 8) ? tod : dow;
        const int   k  = (m < 8) ? (m + 1) : (m - 7);
        const float ang = 6.283185307179586477f * ph * (float)k;
        const float sn = sinf(ang), cs = cosf(ang);
        tok_sh[2 * m]     = sn;
        tok_sh[2 * m + 1] = cs;
        const float g = tanhf(sn * Wg[0] + cs * Wg[1] + bg[0]);  // GATE_BOUND = 1
        gate_sh[m] = g;
        out[GATE_OFF + (size_t)bx * M_ + m] = g;
    }
    __syncthreads();

    // key[a][m] = sin*Wk[a,0] + cos*Wk[a,1] + key_emb[m,a]
    for (int i = tid; i < A_ * M_; i += TPB) {
        const int a = i / M_, m = i - a * M_;
        g_key[(size_t)bx * (A_ * M_) + i] =
            tok_sh[2 * m] * Wk[a * 2] + tok_sh[2 * m + 1] * Wk[a * 2 + 1] + key_emb[m * A_ + a];
    }
    // val[m][d] = gate[m] * val_emb[m,d]
    for (int i = tid; i < M_ * D_; i += TPB) {
        const int m = i >> 6;
        g_val[(size_t)bx * (M_ * D_) + i] = gate_sh[m] * val_emb[i];
    }
    // qs[a] = sum_s step_emb[b,o,s] * Wq[a, D+s] + bq[a]
    if (tid < A_) {
        float acc = bq[tid];
        #pragma unroll
        for (int s = 0; s < S_; s++)
            acc += step_emb[bx * S_ + s] * Wq[tid * (D_ + S_) + D_ + s];
        g_qs[(size_t)bx * A_ + tid] = acc;
    }
}

// ============================================================================
// Kernel 2: main attention. Block = (n-chunk, b). Thread = one n, all 12 o's.
// ============================================================================
__global__ __launch_bounds__(TPB, 3)
void attn_kernel(const float* __restrict__ H,
                 const float* __restrict__ Wq,
                 float* __restrict__ out) {
    extern __shared__ float sh[];
    float* wq_sh  = sh;             // 32*64 = 2048 floats, [a][d]
    float* qs_sh  = sh + 2048;      // 12*32 = 384
    float* key_sh = sh + 2432;      // 12*32*12 = 4608, [o][a][m]
    float* val_sh = sh + 7040;      // 12*12*64 = 9216, [o][m][d]

    const int b   = blockIdx.y;
    const int tid = threadIdx.x;
    const int n   = blockIdx.x * TPB + tid;

    // ---- stage tables into shared ----
    for (int i = tid; i < A_ * D_; i += TPB)
        wq_sh[i] = Wq[(i >> 6) * (D_ + S_) + (i & 63)];
    {
        const float* gq = g_qs + (size_t)b * (O_ * A_);
        for (int i = tid; i < O_ * A_; i += TPB) qs_sh[i] = gq[i];
        const float4* gk = (const float4*)(g_key + (size_t)b * (O_ * A_ * M_));
        float4* k4 = (float4*)key_sh;
        for (int i = tid; i < (O_ * A_ * M_) / 4; i += TPB) k4[i] = gk[i];
        const float4* gv = (const float4*)(g_val + (size_t)b * (O_ * M_ * D_));
        float4* v4 = (float4*)val_sh;
        for (int i = tid; i < (O_ * M_ * D_) / 4; i += TPB) v4[i] = gv[i];
    }
    __syncthreads();

    // ---- H row in f32x2 registers ----
    const float4* Hrow = (const float4*)(H + ((size_t)b * NN + n) * D_);
    unsigned long long hp[D_ / 2];
    #pragma unroll
    for (int i = 0; i < D_ / 4; i++) {
        float4 v = Hrow[i];
        hp[2 * i]     = pack2(v.x, v.y);
        hp[2 * i + 1] = pack2(v.z, v.w);
    }

    // ---- qh[a] = H . Wq[a,:D], once per n (reused for all 12 o's) ----
    float qh[A_];
    #pragma unroll
    for (int a = 0; a < A_; a++) {
        unsigned long long acc = 0ull;
        const ulonglong2* wr = (const ulonglong2*)(wq_sh + a * D_);
        #pragma unroll
        for (int j = 0; j < D_ / 4; j++) {
            ulonglong2 w = wr[j];
            acc = ffma2(hp[2 * j],     w.x, acc);
            acc = ffma2(hp[2 * j + 1], w.y, acc);
        }
        float2 f = unpack2(acc);
        qh[a] = f.x + f.y;
    }

    const unsigned long long ALPHA2 = pack2(0.1f, 0.1f);

    #pragma unroll 1
    for (int o = 0; o < O_; o++) {
        // ---- logits over m (f32x2 m-pairs) ----
        unsigned long long lg[6] = {0ull, 0ull, 0ull, 0ull, 0ull, 0ull};
        const float* qsr = qs_sh + o * A_;
        const float* krw = key_sh + o * A_ * M_;
        #pragma unroll
        for (int a = 0; a < A_; a++) {
            const float qa = qh[a] + qsr[a];
            const unsigned long long q2 = pack2(qa, qa);
            const ulonglong2* kr = (const ulonglong2*)(krw + a * M_);
            ulonglong2 k0 = kr[0], k1 = kr[1], k2 = kr[2];
            lg[0] = ffma2(q2, k0.x, lg[0]);
            lg[1] = ffma2(q2, k0.y, lg[1]);
            lg[2] = ffma2(q2, k1.x, lg[2]);
            lg[3] = ffma2(q2, k1.y, lg[3]);
            lg[4] = ffma2(q2, k2.x, lg[4]);
            lg[5] = ffma2(q2, k2.y, lg[5]);
        }
        float l[M_];
        #pragma unroll
        for (int p = 0; p < 6; p++) {
            float2 f = unpack2(lg[p]);
            l[2 * p] = f.x; l[2 * p + 1] = f.y;
        }
        // ---- softmax (scale folded into exp) ----
        float mx = l[0];
        #pragma unroll
        for (int m = 1; m < M_; m++) mx = fmaxf(mx, l[m]);
        float ssum = 0.f, at[M_];
        #pragma unroll
        for (int m = 0; m < M_; m++) {
            const float e = __expf((l[m] - mx) * SCALE);
            at[m] = e; ssum += e;
        }
        const float inv = __frcp_rn(ssum);
        #pragma unroll
        for (int m = 0; m < M_; m++) at[m] *= inv;

        // ---- write attn (12 floats, 3x STG.128) ----
        float4* aout = (float4*)(out + ATT_OFF + ((size_t)(b * O_ + o) * NN + n) * M_);
        aout[0] = make_float4(at[0], at[1], at[2],  at[3]);
        aout[1] = make_float4(at[4], at[5], at[6],  at[7]);
        aout[2] = make_float4(at[8], at[9], at[10], at[11]);

        unsigned long long am2[M_];
        #pragma unroll
        for (int m = 0; m < M_; m++) am2[m] = pack2(at[m], at[m]);

        // ---- delta + H_time fused per 4-wide d-chunk ----
        float4* hout = (float4*)(out + ((size_t)(b * O_ + o) * NN + n) * D_);
        const ulonglong2* vr = (const ulonglong2*)(val_sh + o * M_ * D_);
        #pragma unroll
        for (int dc = 0; dc < D_ / 4; dc++) {
            unsigned long long a0 = 0ull, a1 = 0ull;
            #pragma unroll
            for (int m = 0; m < M_; m++) {
                ulonglong2 v = vr[m * 16 + dc];
                a0 = ffma2(am2[m], v.x, a0);
                a1 = ffma2(am2[m], v.y, a1);
            }
            const unsigned long long r0 = ffma2(a0, ALPHA2, hp[2 * dc]);
            const unsigned long long r1 = ffma2(a1, ALPHA2, hp[2 * dc + 1]);
            const float2 x = unpack2(r0), y = unpack2(r1);
            hout[dc] = make_float4(x.x, x.y, y.x, y.y);
        }
    }
}

// ============================================================================
extern "C" void kernel_launch(void* const* d_in, const int* in_sizes, int n_in,
                              void* d_out, int out_size) {
    const float* H        = (const float*)d_in[0];
    const float* ts_out   = (const float*)d_in[1];
    const float* step_emb = (const float*)d_in[2];
    const float* key_emb  = (const float*)d_in[3];
    const float* val_emb  = (const float*)d_in[4];
    const float* Wk       = (const float*)d_in[5];
    const float* Wg       = (const float*)d_in[6];
    const float* bg       = (const float*)d_in[7];
    const float* Wq       = (const float*)d_in[8];
    const float* bq       = (const float*)d_in[9];
    float* out = (float*)d_out;

    precompute_kernel<<<B_ * O_, TPB>>>(ts_out, step_emb, key_emb, val_emb,
                                        Wk, Wg, bg, Wq, bq, out);

    const int smem_bytes = (2048 + 384 + 4608 + 9216) * 4;  // 65024 B
    cudaFuncSetAttribute(attn_kernel, cudaFuncAttributeMaxDynamicSharedMemorySize,
                         smem_bytes);
    attn_kernel<<<dim3(NN / TPB, B_), TPB, smem_bytes>>>(H, Wq, out);
}

// round 4
// speedup vs baseline: 1.5675x; 1.5675x over previous
#include <cuda_runtime.h>
#include <math.h>

// Problem constants
#define B_  16
#define NN  4096
#define D_  64
#define O_  12
#define S_  32
#define M_  12
#define A_  32

// Output layout: H_time [B,O,N,D] ++ attn [B,O,N,M] ++ gate [B,O,M]
#define ATT_OFF  50331648ull   // B*O*N*D
#define GATE_OFF 59768832ull   // + B*O*N*M
#define SCALE 0.17677669529663688f   // 1/sqrt(32)

// Scratch (no allocations allowed -> __device__ globals)
__device__ float g_key[B_*O_*A_*M_];     // [b][o][a][m]
__device__ float g_val[B_*O_*M_*D_];     // [b][o][m][d]  (gate folded in)
__device__ float g_c  [B_*O_*M_];        // [b][o][m]     (qs . key folded in)
__device__ float g_Q  [(size_t)B_*NN*A_];// [b][n][a]     (qh = H . Wq[:, :D])

// ---- f32x2 helpers ----
__device__ __forceinline__ unsigned long long ffma2(unsigned long long a,
                                                    unsigned long long b,
                                                    unsigned long long c) {
    unsigned long long d;
    asm("fma.rn.f32x2 %0, %1, %2, %3;" : "=l"(d) : "l"(a), "l"(b), "l"(c));
    return d;
}
__device__ __forceinline__ unsigned long long pack2(float x, float y) {
    unsigned long long r;
    asm("mov.b64 %0, {%1, %2};" : "=l"(r) : "r"(__float_as_uint(x)), "r"(__float_as_uint(y)));
    return r;
}
__device__ __forceinline__ float2 unpack2(unsigned long long v) {
    unsigned int lo, hi;
    asm("mov.b64 {%0, %1}, %2;" : "=r"(lo), "=r"(hi) : "l"(v));
    return make_float2(__uint_as_float(lo), __uint_as_float(hi));
}

// ============================================================================
// Kernel 1: per-(b,o) tiny precompute (tokens, key, gate, val, c = qs.key)
// ============================================================================
__global__ void precompute_kernel(const float* __restrict__ ts_out,
                                  const float* __restrict__ step_emb,
                                  const float* __restrict__ key_emb,
                                  const float* __restrict__ val_emb,
                                  const float* __restrict__ Wk,
                                  const float* __restrict__ Wg,
                                  const float* __restrict__ bg,
                                  const float* __restrict__ Wq,
                                  const float* __restrict__ bq,
                                  float* __restrict__ out) {
    __shared__ float tok_sh[M_ * 2];
    __shared__ float gate_sh[M_];
    __shared__ float key_s[A_ * M_];
    __shared__ float qs_sh[A_];
    const int bx  = blockIdx.x;      // bx = b*O + o
    const int tid = threadIdx.x;

    const float tod = ts_out[bx * 2 + 0];
    const float dow = ts_out[bx * 2 + 1];

    if (tid < M_) {
        const int m   = tid;
        const float ph = (m < 8) ? tod : dow;
        const int   k  = (m < 8) ? (m + 1) : (m - 7);
        const float ang = 6.283185307179586477f * ph * (float)k;
        const float sn = sinf(ang), cs = cosf(ang);
        tok_sh[2 * m]     = sn;
        tok_sh[2 * m + 1] = cs;
        const float g = tanhf(sn * Wg[0] + cs * Wg[1] + bg[0]);  // GATE_BOUND=1
        gate_sh[m] = g;
        out[GATE_OFF + (size_t)bx * M_ + m] = g;
    }
    // qs[a] = sum_s step_emb[b,o,s] * Wq[a, D+s] + bq[a]
    if (tid >= 32 && tid < 64) {
        const int a = tid - 32;
        float acc = bq[a];
        #pragma unroll
        for (int s = 0; s < S_; s++)
            acc += step_emb[bx * S_ + s] * Wq[a * (D_ + S_) + D_ + s];
        qs_sh[a] = acc;
    }
    __syncthreads();

    // key[a][m] = sin*Wk[a,0] + cos*Wk[a,1] + key_emb[m,a]
    for (int i = tid; i < A_ * M_; i += 128) {
        const int a = i / M_, m = i - a * M_;
        const float kv =
            tok_sh[2 * m] * Wk[a * 2] + tok_sh[2 * m + 1] * Wk[a * 2 + 1] + key_emb[m * A_ + a];
        key_s[i] = kv;
        g_key[(size_t)bx * (A_ * M_) + i] = kv;
    }
    // val[m][d] = gate[m] * val_emb[m,d]
    for (int i = tid; i < M_ * D_; i += 128) {
        const int m = i >> 6;
        g_val[(size_t)bx * (M_ * D_) + i] = gate_sh[m] * val_emb[i];
    }
    __syncthreads();

    // c[m] = sum_a qs[a] * key[a][m]
    if (tid < M_) {
        float acc = 0.f;
        #pragma unroll
        for (int a = 0; a < A_; a++) acc += qs_sh[a] * key_s[a * M_ + tid];
        g_c[(size_t)bx * M_ + tid] = acc;
    }
}

// ============================================================================
// Kernel 2: qh[b,n,a] = H[b,n,:] . Wq[a,:D]   (thread per n)
// ============================================================================
__global__ __launch_bounds__(128)
void qh_kernel(const float* __restrict__ H, const float* __restrict__ Wq) {
    __shared__ float wq_sh[A_ * D_];   // [a][d]
    const int b   = blockIdx.y;
    const int tid = threadIdx.x;
    const int n   = blockIdx.x * 128 + tid;

    for (int i = tid; i < A_ * D_; i += 128)
        wq_sh[i] = Wq[(i >> 6) * (D_ + S_) + (i & 63)];
    __syncthreads();

    const float4* Hrow = (const float4*)(H + ((size_t)b * NN + n) * D_);
    unsigned long long hp[D_ / 2];
    #pragma unroll
    for (int i = 0; i < D_ / 4; i++) {
        float4 v = Hrow[i];
        hp[2 * i]     = pack2(v.x, v.y);
        hp[2 * i + 1] = pack2(v.z, v.w);
    }

    float qh[A_];
    #pragma unroll
    for (int a = 0; a < A_; a++) {
        unsigned long long acc = 0ull;
        const ulonglong2* wr = (const ulonglong2*)(wq_sh + a * D_);
        #pragma unroll
        for (int j = 0; j < D_ / 4; j++) {
            ulonglong2 w = wr[j];
            acc = ffma2(hp[2 * j],     w.x, acc);
            acc = ffma2(hp[2 * j + 1], w.y, acc);
        }
        float2 f = unpack2(acc);
        qh[a] = f.x + f.y;
    }

    float4* Qo = (float4*)(g_Q + ((size_t)b * NN + n) * A_);
    #pragma unroll
    for (int ac = 0; ac < A_ / 4; ac++)
        Qo[ac] = make_float4(qh[4 * ac], qh[4 * ac + 1], qh[4 * ac + 2], qh[4 * ac + 3]);
}

// ============================================================================
// Kernel 3: main. Block = 32 n x 6 o (o-half), 256 threads, two phases.
//   smem carve (floats):
//     key_sh   [0,     2304)   [ol][a][m]
//     val_sh   [2304,  6912)   [ol][m][d]
//     c_sh     [6912,  6984)   [ol][m]
//     at_sh    [6984,  9288)   [ol][n][m]
//     qh_sh    [9288, 10344)   [n][a] stride 33 (conflict-free)
//     h_sh     [10344,12520)   [n][d] stride 68 (16B-aligned rows)
// ============================================================================
#define SMEM_FLOATS 12520

__global__ __launch_bounds__(256, 4)
void attn_kernel(const float* __restrict__ H, float* __restrict__ out) {
    extern __shared__ float sh[];
    float* key_sh = sh;
    float* val_sh = sh + 2304;
    float* c_sh   = sh + 6912;
    float* at_sh  = sh + 6984;
    float* qh_sh  = sh + 9288;
    float* h_sh   = sh + 10344;

    const int t  = threadIdx.x;
    const int b  = blockIdx.z;
    const int oh = blockIdx.y;          // o-half: 0 or 1
    const int n0 = blockIdx.x * 32;

    // ---- stage tables (coalesced) ----
    {
        const float4* gk = (const float4*)(g_key + (size_t)(b * O_ + oh * 6) * (A_ * M_));
        float4* k4 = (float4*)key_sh;
        for (int i = t; i < 2304 / 4; i += 256) k4[i] = gk[i];
        const float4* gv = (const float4*)(g_val + (size_t)(b * O_ + oh * 6) * (M_ * D_));
        float4* v4 = (float4*)val_sh;
        for (int i = t; i < 4608 / 4; i += 256) v4[i] = gv[i];
        if (t < 72) c_sh[t] = g_c[(size_t)(b * O_ + oh * 6) * M_ + t];
        // qh tile: 32 n x 32 a, scalar stores into stride-33 rows
        const float* Qb = g_Q + ((size_t)b * NN + n0) * A_;
        for (int i = t; i < 1024; i += 256)
            qh_sh[(i >> 5) * 33 + (i & 31)] = Qb[i];
    }
    __syncthreads();

    if (t >= 192) {
        // ---- 64 threads stage H tile (overlapped with phase A) ----
        const int tt = t - 192;
        const float4* Hg = (const float4*)(H + ((size_t)b * NN + n0) * D_);
        for (int i = tt; i < 512; i += 64) {
            float4 v = Hg[i];
            *(float4*)(h_sh + (i >> 4) * 68 + (i & 15) * 4) = v;
        }
    } else {
        // ---- phase A: thread per (n, o): logits, softmax, attn store ----
        const int nl = t & 31;
        const int ol = t >> 5;   // 0..5
        const int o  = oh * 6 + ol;

        unsigned long long lg[6];
        const float* cp = c_sh + ol * M_;
        #pragma unroll
        for (int p = 0; p < 6; p++) lg[p] = pack2(cp[2 * p], cp[2 * p + 1]);

        const float* kp = key_sh + ol * (A_ * M_);
        const float* qp = qh_sh + nl * 33;
        #pragma unroll
        for (int a = 0; a < A_; a++) {
            const float qa = qp[a];
            const unsigned long long q2 = pack2(qa, qa);
            const ulonglong2* kr = (const ulonglong2*)(kp + a * M_);
            ulonglong2 k0 = kr[0], k1 = kr[1], k2 = kr[2];
            lg[0] = ffma2(q2, k0.x, lg[0]);
            lg[1] = ffma2(q2, k0.y, lg[1]);
            lg[2] = ffma2(q2, k1.x, lg[2]);
            lg[3] = ffma2(q2, k1.y, lg[3]);
            lg[4] = ffma2(q2, k2.x, lg[4]);
            lg[5] = ffma2(q2, k2.y, lg[5]);
        }
        float l[M_];
        #pragma unroll
        for (int p = 0; p < 6; p++) {
            float2 f = unpack2(lg[p]);
            l[2 * p] = f.x; l[2 * p + 1] = f.y;
        }
        float mx = l[0];
        #pragma unroll
        for (int m = 1; m < M_; m++) mx = fmaxf(mx, l[m]);
        float ssum = 0.f, at[M_];
        #pragma unroll
        for (int m = 0; m < M_; m++) {
            const float e = __expf((l[m] - mx) * SCALE);
            at[m] = e; ssum += e;
        }
        const float inv = __frcp_rn(ssum);
        #pragma unroll
        for (int m = 0; m < M_; m++) at[m] *= inv;

        // attn output (warp = 32 consecutive n, one o -> 1536B contiguous)
        float4* ao = (float4*)(out + ATT_OFF + ((size_t)(b * O_ + o) * NN + n0 + nl) * M_);
        ao[0] = make_float4(at[0], at[1], at[2],  at[3]);
        ao[1] = make_float4(at[4], at[5], at[6],  at[7]);
        ao[2] = make_float4(at[8], at[9], at[10], at[11]);

        // stash for phase B
        float4* as = (float4*)(at_sh + (ol * 32 + nl) * M_);
        as[0] = make_float4(at[0], at[1], at[2],  at[3]);
        as[1] = make_float4(at[4], at[5], at[6],  at[7]);
        as[2] = make_float4(at[8], at[9], at[10], at[11]);
    }
    __syncthreads();

    // ---- phase B: lane = (n pair x 16 d-chunks) -> fully coalesced I/O ----
    const int dq  = t & 15;        // 16B chunk of d (4 floats)
    const int nn0 = t >> 4;        // 0..15
    const unsigned long long ALPHA2 = pack2(0.1f, 0.1f);

    for (int ol = 0; ol < 6; ol++) {
        const int o = oh * 6 + ol;
        const float* vp = val_sh + ol * (M_ * D_) + dq * 4;
        #pragma unroll
        for (int pass = 0; pass < 2; pass++) {
            const int nn = nn0 + pass * 16;
            const float4* ap4 = (const float4*)(at_sh + (ol * 32 + nn) * M_);
            float4 u0 = ap4[0], u1 = ap4[1], u2 = ap4[2];
            unsigned long long a0 = 0ull, a1 = 0ull;
            const ulonglong2* vr = (const ulonglong2*)vp;
            {
                ulonglong2 v;
                v = vr[0 * 8];  { unsigned long long am = pack2(u0.x, u0.x); a0 = ffma2(am, v.x, a0); a1 = ffma2(am, v.y, a1); }
                v = vr[1 * 8];  { unsigned long long am = pack2(u0.y, u0.y); a0 = ffma2(am, v.x, a0); a1 = ffma2(am, v.y, a1); }
                v = vr[2 * 8];  { unsigned long long am = pack2(u0.z, u0.z); a0 = ffma2(am, v.x, a0); a1 = ffma2(am, v.y, a1); }
                v = vr[3 * 8];  { unsigned long long am = pack2(u0.w, u0.w); a0 = ffma2(am, v.x, a0); a1 = ffma2(am, v.y, a1); }
                v = vr[4 * 8];  { unsigned long long am = pack2(u1.x, u1.x); a0 = ffma2(am, v.x, a0); a1 = ffma2(am, v.y, a1); }
                v = vr[5 * 8];  { unsigned long long am = pack2(u1.y, u1.y); a0 = ffma2(am, v.x, a0); a1 = ffma2(am, v.y, a1); }
                v = vr[6 * 8];  { unsigned long long am = pack2(u1.z, u1.z); a0 = ffma2(am, v.x, a0); a1 = ffma2(am, v.y, a1); }
                v = vr[7 * 8];  { unsigned long long am = pack2(u1.w, u1.w); a0 = ffma2(am, v.x, a0); a1 = ffma2(am, v.y, a1); }
                v = vr[8 * 8];  { unsigned long long am = pack2(u2.x, u2.x); a0 = ffma2(am, v.x, a0); a1 = ffma2(am, v.y, a1); }
                v = vr[9 * 8];  { unsigned long long am = pack2(u2.y, u2.y); a0 = ffma2(am, v.x, a0); a1 = ffma2(am, v.y, a1); }
                v = vr[10 * 8]; { unsigned long long am = pack2(u2.z, u2.z); a0 = ffma2(am, v.x, a0); a1 = ffma2(am, v.y, a1); }
                v = vr[11 * 8]; { unsigned long long am = pack2(u2.w, u2.w); a0 = ffma2(am, v.x, a0); a1 = ffma2(am, v.y, a1); }
            }
            // H_time = H + 0.1 * delta   (H from conflict-free smem)
            const ulonglong2 h = *(const ulonglong2*)(h_sh + nn * 68 + dq * 4);
            const unsigned long long r0 = ffma2(a0, ALPHA2, h.x);
            const unsigned long long r1 = ffma2(a1, ALPHA2, h.y);
            const float2 x = unpack2(r0), y = unpack2(r1);
            // warp writes 2 full n-rows: contiguous 512B
            *(float4*)(out + ((size_t)(b * O_ + o) * NN + n0 + nn) * D_ + dq * 4) =
                make_float4(x.x, x.y, y.x, y.y);
        }
    }
}

// ============================================================================
extern "C" void kernel_launch(void* const* d_in, const int* in_sizes, int n_in,
                              void* d_out, int out_size) {
    const float* H        = (const float*)d_in[0];
    const float* ts_out   = (const float*)d_in[1];
    const float* step_emb = (const float*)d_in[2];
    const float* key_emb  = (const float*)d_in[3];
    const float* val_emb  = (const float*)d_in[4];
    const float* Wk       = (const float*)d_in[5];
    const float* Wg       = (const float*)d_in[6];
    const float* bg       = (const float*)d_in[7];
    const float* Wq       = (const float*)d_in[8];
    const float* bq       = (const float*)d_in[9];
    float* out = (float*)d_out;

    precompute_kernel<<<B_ * O_, 128>>>(ts_out, step_emb, key_emb, val_emb,
                                        Wk, Wg, bg, Wq, bq, out);
    qh_kernel<<<dim3(NN / 128, B_), 128>>>(H, Wq);

    const int smem_bytes = SMEM_FLOATS * 4;  // 50080 B
    cudaFuncSetAttribute(attn_kernel, cudaFuncAttributeMaxDynamicSharedMemorySize,
                         smem_bytes);
    attn_kernel<<<dim3(NN / 32, 2, B_), 256, smem_bytes>>>(H, out);
}

// round 6
// speedup vs baseline: 2.2086x; 1.4090x over previous
#include <cuda_runtime.h>
#include <math.h>

// Problem constants
#define B_  16
#define NN  4096
#define D_  64
#define O_  12
#define S_  32
#define M_  12
#define A_  32

// Output layout: H_time [B,O,N,D] ++ attn [B,O,N,M] ++ gate [B,O,M]
#define ATT_OFF  50331648ull
#define GATE_OFF 59768832ull
#define SCALE 0.17677669529663688f   // 1/sqrt(32)

// Scratch
__device__ float g_key[B_*O_*A_*M_];      // [b][o][a][m]
__device__ float g_val[B_*O_*M_*D_];      // [b][o][m][d]  (gate folded in)
__device__ float g_c  [B_*O_*M_];         // [b][o][m]     (qs . key)
__device__ float g_Q  [(size_t)B_*NN*A_]; // [b][n][a]

typedef unsigned long long ull;

__device__ __forceinline__ ull ffma2(ull a, ull b, ull c) {
    ull d;
    asm("fma.rn.f32x2 %0, %1, %2, %3;" : "=l"(d) : "l"(a), "l"(b), "l"(c));
    return d;
}
__device__ __forceinline__ ull pack2(float x, float y) {
    ull r;
    asm("mov.b64 %0, {%1, %2};" : "=l"(r) : "r"(__float_as_uint(x)), "r"(__float_as_uint(y)));
    return r;
}
__device__ __forceinline__ float2 unpack2(ull v) {
    unsigned int lo, hi;
    asm("mov.b64 {%0, %1}, %2;" : "=r"(lo), "=r"(hi) : "l"(v));
    return make_float2(__uint_as_float(lo), __uint_as_float(hi));
}

// ============================================================================
// Kernel 1 (fused): blockIdx.x < 32 -> qh ; blockIdx.x in {32,33} -> precompute
// ============================================================================
__global__ __launch_bounds__(128)
void prep_kernel(const float* __restrict__ H,
                 const float* __restrict__ ts_out,
                 const float* __restrict__ step_emb,
                 const float* __restrict__ key_emb,
                 const float* __restrict__ val_emb,
                 const float* __restrict__ Wk,
                 const float* __restrict__ Wg,
                 const float* __restrict__ bg,
                 const float* __restrict__ Wq,
                 const float* __restrict__ bq,
                 float* __restrict__ out) {
    __shared__ float wq_sh[A_ * D_];   // qh: [a][d] 2048 | precompute: first 1024 = Wq[:,D:] [a][s]
    const int b   = blockIdx.y;
    const int tid = threadIdx.x;

    if (blockIdx.x < 32) {
        // ---------------- qh: thread per n ----------------
        const int n = blockIdx.x * 128 + tid;
        for (int i = tid; i < A_ * D_; i += 128)
            wq_sh[i] = Wq[(i >> 6) * (D_ + S_) + (i & 63)];
        __syncthreads();

        const float4* Hrow = (const float4*)(H + ((size_t)b * NN + n) * D_);
        ull hp[D_ / 2];
        #pragma unroll
        for (int i = 0; i < D_ / 4; i++) {
            float4 v = Hrow[i];
            hp[2 * i]     = pack2(v.x, v.y);
            hp[2 * i + 1] = pack2(v.z, v.w);
        }
        float qh[A_];
        #pragma unroll
        for (int a = 0; a < A_; a++) {
            ull acc = 0ull;
            const ulonglong2* wr = (const ulonglong2*)(wq_sh + a * D_);
            #pragma unroll
            for (int j = 0; j < D_ / 4; j++) {
                ulonglong2 w = wr[j];
                acc = ffma2(hp[2 * j],     w.x, acc);
                acc = ffma2(hp[2 * j + 1], w.y, acc);
            }
            float2 f = unpack2(acc);
            qh[a] = f.x + f.y;
        }
        float4* Qo = (float4*)(g_Q + ((size_t)b * NN + n) * A_);
        #pragma unroll
        for (int ac = 0; ac < A_ / 4; ac++)
            Qo[ac] = make_float4(qh[4*ac], qh[4*ac+1], qh[4*ac+2], qh[4*ac+3]);
    } else {
        // ---------------- precompute: 6 o's per block ----------------
        __shared__ float tok_sh[M_ * 2];
        __shared__ float gate_sh[M_];
        __shared__ float key_s[A_ * M_];
        __shared__ float qs_sh[A_];
        __shared__ float step_sh[S_];

        // stage Wq[:, D:] coalesced: [a][s] in wq_sh[0..1024)
        for (int i = tid; i < A_ * S_; i += 128)
            wq_sh[i] = Wq[(i >> 5) * (D_ + S_) + D_ + (i & 31)];
        __syncthreads();

        const int g = blockIdx.x - 32;          // 0 or 1
        for (int ol = 0; ol < 6; ol++) {
            const int o  = g * 6 + ol;
            const int bx = b * O_ + o;

            if (tid < M_) {
                const int m   = tid;
                const float ph = (m < 8) ? ts_out[bx * 2] : ts_out[bx * 2 + 1];
                const int   k  = (m < 8) ? (m + 1) : (m - 7);
                const float ang = 6.283185307179586477f * ph * (float)k;
                const float sn = sinf(ang), cs = cosf(ang);
                tok_sh[2 * m]     = sn;
                tok_sh[2 * m + 1] = cs;
                const float gt = tanhf(sn * Wg[0] + cs * Wg[1] + bg[0]);
                gate_sh[m] = gt;
                out[GATE_OFF + (size_t)bx * M_ + m] = gt;
            }
            if (tid >= 64 && tid < 96) step_sh[tid - 64] = step_emb[bx * S_ + tid - 64];
            __syncthreads();

            if (tid >= 32 && tid < 64) {
                const int a = tid - 32;
                float acc = bq[a];
                #pragma unroll
                for (int s = 0; s < S_; s++) acc += step_sh[s] * wq_sh[a * S_ + s];
                qs_sh[a] = acc;
            }
            for (int i = tid; i < A_ * M_; i += 128) {
                const int a = i / M_, m = i - a * M_;
                const float kv = tok_sh[2 * m] * Wk[a * 2] + tok_sh[2 * m + 1] * Wk[a * 2 + 1]
                               + key_emb[m * A_ + a];
                key_s[i] = kv;
                g_key[(size_t)bx * (A_ * M_) + i] = kv;
            }
            for (int i = tid; i < M_ * D_; i += 128)
                g_val[(size_t)bx * (M_ * D_) + i] = gate_sh[i >> 6] * val_emb[i];
            __syncthreads();

            if (tid < M_) {
                float acc = 0.f;
                #pragma unroll
                for (int a = 0; a < A_; a++) acc += qs_sh[a] * key_s[a * M_ + tid];
                g_c[(size_t)bx * M_ + tid] = acc;
            }
            __syncthreads();
        }
    }
}

// ============================================================================
// Kernel 2: main. Block = 64 n x 6 o (o-half), 256 threads.
//   smem (floats): key 2304 | val 4608 | c 72 | at 6*64*12=4608 | qh 64*33=2112
// ============================================================================
#define SMEM_FLOATS 13704

__global__ __launch_bounds__(256, 4)
void attn_kernel(const float* __restrict__ H, float* __restrict__ out) {
    extern __shared__ float sh[];
    float* key_sh = sh;             // [ol][a][m]
    float* val_sh = sh + 2304;      // [ol][m][d]
    float* c_sh   = sh + 6912;      // [ol][m]
    float* at_sh  = sh + 6984;      // [ol*64+nl][m]  stride 12
    float* qh_sh  = sh + 11592;     // [nl][a] stride 33

    const int t  = threadIdx.x;
    const int b  = blockIdx.z;
    const int oh = blockIdx.y;
    const int n0 = blockIdx.x * 64;

    // ---- stage (coalesced) ----
    {
        const float4* gk = (const float4*)(g_key + (size_t)(b * O_ + oh * 6) * (A_ * M_));
        float4* k4 = (float4*)key_sh;
        for (int i = t; i < 576; i += 256) k4[i] = gk[i];
        const float4* gv = (const float4*)(g_val + (size_t)(b * O_ + oh * 6) * (M_ * D_));
        float4* v4 = (float4*)val_sh;
        for (int i = t; i < 1152; i += 256) v4[i] = gv[i];
        if (t < 72) c_sh[t] = g_c[(size_t)(b * O_ + oh * 6) * M_ + t];
        const float* Qb = g_Q + ((size_t)b * NN + n0) * A_;
        for (int i = t; i < 2048; i += 256)
            qh_sh[(i >> 5) * 33 + (i & 31)] = Qb[i];
    }
    __syncthreads();

    // ---- phase A: job = (nl, ol); 384 jobs over 256 threads ----
    for (int j = t; j < 384; j += 256) {
        const int nl = j & 63;
        const int ol = j >> 6;
        const int o  = oh * 6 + ol;

        ull lg[6];
        const float* cp = c_sh + ol * M_;
        #pragma unroll
        for (int p = 0; p < 6; p++) lg[p] = pack2(cp[2 * p], cp[2 * p + 1]);

        const float* kp = key_sh + ol * (A_ * M_);
        const float* qp = qh_sh + nl * 33;
        #pragma unroll
        for (int a = 0; a < A_; a++) {
            const float qa = qp[a];
            const ull q2 = pack2(qa, qa);
            const ulonglong2* kr = (const ulonglong2*)(kp + a * M_);
            ulonglong2 k0 = kr[0], k1 = kr[1], k2 = kr[2];
            lg[0] = ffma2(q2, k0.x, lg[0]);
            lg[1] = ffma2(q2, k0.y, lg[1]);
            lg[2] = ffma2(q2, k1.x, lg[2]);
            lg[3] = ffma2(q2, k1.y, lg[3]);
            lg[4] = ffma2(q2, k2.x, lg[4]);
            lg[5] = ffma2(q2, k2.y, lg[5]);
        }
        float l[M_];
        #pragma unroll
        for (int p = 0; p < 6; p++) {
            float2 f = unpack2(lg[p]);
            l[2 * p] = f.x; l[2 * p + 1] = f.y;
        }
        float mx = l[0];
        #pragma unroll
        for (int m = 1; m < M_; m++) mx = fmaxf(mx, l[m]);
        float ssum = 0.f, at[M_];
        #pragma unroll
        for (int m = 0; m < M_; m++) {
            const float e = __expf((l[m] - mx) * SCALE);
            at[m] = e; ssum += e;
        }
        const float inv = __frcp_rn(ssum);
        #pragma unroll
        for (int m = 0; m < M_; m++) at[m] *= inv;

        float4* ao = (float4*)(out + ATT_OFF + ((size_t)(b * O_ + o) * NN + n0 + nl) * M_);
        ao[0] = make_float4(at[0], at[1], at[2],  at[3]);
        ao[1] = make_float4(at[4], at[5], at[6],  at[7]);
        ao[2] = make_float4(at[8], at[9], at[10], at[11]);

        float4* as = (float4*)(at_sh + (ol * 64 + nl) * M_);
        as[0] = make_float4(at[0], at[1], at[2],  at[3]);
        as[1] = make_float4(at[4], at[5], at[6],  at[7]);
        as[2] = make_float4(at[8], at[9], at[10], at[11]);
    }
    __syncthreads();

    // ---- phase B: thread = (dq2 8B-chunk, nn0); val hoisted per o ----
    const int dq2 = t & 31;        // d-pair index (2 floats)
    const int nn0 = t >> 5;        // 0..7
    const ull ALPHA2 = pack2(0.1f, 0.1f);

    // preload H pairs for this thread's 8 rows (reused across all 6 o)
    ull hh[8];
    #pragma unroll
    for (int p = 0; p < 8; p++)
        hh[p] = *(const ull*)(H + ((size_t)b * NN + n0 + p * 8 + nn0) * D_ + dq2 * 2);

    #pragma unroll 1
    for (int ol = 0; ol < 6; ol++) {
        const int o = oh * 6 + ol;
        ull vv[M_];
        const float* vb = val_sh + ol * (M_ * D_) + dq2 * 2;
        #pragma unroll
        for (int m = 0; m < M_; m++) vv[m] = *(const ull*)(vb + m * D_);

        const float* atb = at_sh + ol * 64 * M_;
        float* ob = out + ((size_t)(b * O_ + o) * NN + n0) * D_ + dq2 * 2;
        #pragma unroll
        for (int p = 0; p < 8; p++) {
            const int nn = p * 8 + nn0;
            const float4* ap = (const float4*)(atb + nn * M_);
            float4 u0 = ap[0], u1 = ap[1], u2 = ap[2];
            ull acc = 0ull;
            acc = ffma2(pack2(u0.x, u0.x), vv[0],  acc);
            acc = ffma2(pack2(u0.y, u0.y), vv[1],  acc);
            acc = ffma2(pack2(u0.z, u0.z), vv[2],  acc);
            acc = ffma2(pack2(u0.w, u0.w), vv[3],  acc);
            acc = ffma2(pack2(u1.x, u1.x), vv[4],  acc);
            acc = ffma2(pack2(u1.y, u1.y), vv[5],  acc);
            acc = ffma2(pack2(u1.z, u1.z), vv[6],  acc);
            acc = ffma2(pack2(u1.w, u1.w), vv[7],  acc);
            acc = ffma2(pack2(u2.x, u2.x), vv[8],  acc);
            acc = ffma2(pack2(u2.y, u2.y), vv[9],  acc);
            acc = ffma2(pack2(u2.z, u2.z), vv[10], acc);
            acc = ffma2(pack2(u2.w, u2.w), vv[11], acc);
            *(ull*)(ob + (size_t)nn * D_) = ffma2(acc, ALPHA2, hh[p]);
        }
    }
}

// ============================================================================
extern "C" void kernel_launch(void* const* d_in, const int* in_sizes, int n_in,
                              void* d_out, int out_size) {
    const float* H        = (const float*)d_in[0];
    const float* ts_out   = (const float*)d_in[1];
    const float* step_emb = (const float*)d_in[2];
    const float* key_emb  = (const float*)d_in[3];
    const float* val_emb  = (const float*)d_in[4];
    const float* Wk       = (const float*)d_in[5];
    const float* Wg       = (const float*)d_in[6];
    const float* bg       = (const float*)d_in[7];
    const float* Wq       = (const float*)d_in[8];
    const float* bq       = (const float*)d_in[9];
    float* out = (float*)d_out;

    prep_kernel<<<dim3(34, B_), 128>>>(H, ts_out, step_emb, key_emb, val_emb,
                                       Wk, Wg, bg, Wq, bq, out);

    const int smem_bytes = SMEM_FLOATS * 4;  // 54816 B
    cudaFuncSetAttribute(attn_kernel, cudaFuncAttributeMaxDynamicSharedMemorySize,
                         smem_bytes);
    attn_kernel<<<dim3(NN / 64, 2, B_), 256, smem_bytes>>>(H, out);
}